// round 2
// baseline (speedup 1.0000x reference)
#include <cuda_runtime.h>

#define NN 100000
#define EE 1600000
#define FF 128
#define DD 64
#define GG 512

// ---------------- device scratch (no allocation allowed) ----------------
__device__ __align__(16) float g_y[NN * DD];     // projected features (x@W1 or hbn@W1b)
__device__ __align__(16) float g_agg[NN * DD];   // edge aggregation target
__device__ __align__(16) float g_h[NN * DD];     // pre-BN relu output
__device__ __align__(16) float g_hbn[NN * DD];   // post-BN output of layer 0
__device__ double g_sum[DD];
__device__ double g_sq[DD];
__device__ __align__(16) float g_bnp[2 * DD];    // [scale(64), shift(64)]
__device__ __align__(16) float g_pool[2 * GG * DD];

__device__ __forceinline__ void red4(float4* p, float x, float y, float z, float w) {
    asm volatile("red.global.add.v4.f32 [%0], {%1,%2,%3,%4};"
                 :: "l"(p), "f"(x), "f"(y), "f"(z), "f"(w) : "memory");
}

// ---------------- zero scratch ----------------
__global__ void zero_kernel(int mode) {
    int t = blockIdx.x * blockDim.x + threadIdx.x;
    if (t < NN * 16) reinterpret_cast<float4*>(g_agg)[t] = make_float4(0.f, 0.f, 0.f, 0.f);
    if (t < DD) { g_sum[t] = 0.0; g_sq[t] = 0.0; }
    if (mode == 0 && t < 2 * GG * 16)
        reinterpret_cast<float4*>(g_pool)[t] = make_float4(0.f, 0.f, 0.f, 0.f);
}

// ---------------- C[N x 64] = A[N x K] @ W[K x 64]  ->  g_y ----------------
template <int K>
__global__ void gemm_kernel(const float* __restrict__ Ain, const float* __restrict__ W) {
    __shared__ float As[64 * 68];
    __shared__ float Ws[64 * 64];
    const float* A = Ain ? Ain : g_hbn;
    int base = blockIdx.x * 64;
    int tid = threadIdx.x;
    int ty = tid >> 4, tx = tid & 15;
    float acc[4][4] = {};
    for (int kc = 0; kc < K; kc += 64) {
        for (int i = tid; i < 64 * 64; i += 256) {
            int n = i >> 6, k = i & 63;
            int gn = base + n;
            As[n * 68 + k] = (gn < NN) ? A[(size_t)gn * K + kc + k] : 0.f;
        }
        for (int i = tid; i < 64 * 64; i += 256) {
            int k = i >> 6, j = i & 63;
            Ws[k * 64 + j] = W[(size_t)(kc + k) * 64 + j];
        }
        __syncthreads();
#pragma unroll 8
        for (int k = 0; k < 64; k++) {
            float a[4];
#pragma unroll
            for (int r = 0; r < 4; r++) a[r] = As[(ty * 4 + r) * 68 + k];
            float4 b = *reinterpret_cast<const float4*>(&Ws[k * 64 + tx * 4]);
            float bv[4] = {b.x, b.y, b.z, b.w};
#pragma unroll
            for (int r = 0; r < 4; r++)
#pragma unroll
                for (int c = 0; c < 4; c++) acc[r][c] += a[r] * bv[c];
        }
        __syncthreads();
    }
#pragma unroll
    for (int r = 0; r < 4; r++) {
        int gn = base + ty * 4 + r;
        if (gn < NN) {
            float4 v = make_float4(acc[r][0], acc[r][1], acc[r][2], acc[r][3]);
            reinterpret_cast<float4*>(g_y)[gn * 16 + tx] = v;
        }
    }
}

// ---------------- edge scatter: g_agg[dst] += ew * g_y[src] ----------------
__global__ void scatter_kernel(const int* __restrict__ ei, const float* __restrict__ ew) {
    int t = blockIdx.x * blockDim.x + threadIdx.x;
    if (t >= EE * 16) return;
    int e = t >> 4, c = t & 15;
    int src = ei[e];
    int dst = ei[EE + e];
    float w = ew[e];
    float4 v = reinterpret_cast<const float4*>(g_y)[src * 16 + c];
    red4(&reinterpret_cast<float4*>(g_agg)[dst * 16 + c], w * v.x, w * v.y, w * v.z, w * v.w);
}

// ---------------- node MLP tail: r = relu(relu(y+agg+b1) @ W2 + b2); stats ----------------
__global__ void mlp2_kernel(const float* __restrict__ b1, const float* __restrict__ W2,
                            const float* __restrict__ b2) {
    __shared__ float Ts[64 * 68];
    __shared__ float Ws[64 * 64];
    __shared__ float B2s[64];
    int base = blockIdx.x * 64;
    int tid = threadIdx.x;
    for (int i = tid; i < 64 * 64; i += 256) Ws[i] = W2[i];
    if (tid < 64) B2s[tid] = b2[tid];
    for (int i = tid; i < 64 * 64; i += 256) {
        int n = i >> 6, k = i & 63;
        int gn = base + n;
        float v = 0.f;
        if (gn < NN) v = fmaxf(g_y[gn * 64 + k] + g_agg[gn * 64 + k] + b1[k], 0.f);
        Ts[n * 68 + k] = v;
    }
    __syncthreads();
    int ty = tid >> 4, tx = tid & 15;
    float acc[4][4] = {};
#pragma unroll 8
    for (int k = 0; k < 64; k++) {
        float a[4];
#pragma unroll
        for (int r = 0; r < 4; r++) a[r] = Ts[(ty * 4 + r) * 68 + k];
        float4 b = *reinterpret_cast<const float4*>(&Ws[k * 64 + tx * 4]);
        float bv[4] = {b.x, b.y, b.z, b.w};
#pragma unroll
        for (int r = 0; r < 4; r++)
#pragma unroll
            for (int c = 0; c < 4; c++) acc[r][c] += a[r] * bv[c];
    }
    __syncthreads();  // done reading Ts; reuse it for the result tile
    float4 bb = *reinterpret_cast<const float4*>(&B2s[tx * 4]);
    float bbv[4] = {bb.x, bb.y, bb.z, bb.w};
#pragma unroll
    for (int r = 0; r < 4; r++) {
        int gn = base + ty * 4 + r;
#pragma unroll
        for (int c = 0; c < 4; c++) {
            float v = (gn < NN) ? fmaxf(acc[r][c] + bbv[c], 0.f) : 0.f;
            Ts[(ty * 4 + r) * 68 + tx * 4 + c] = v;
        }
    }
    __syncthreads();
    for (int i = tid; i < 64 * 64; i += 256) {
        int n = i >> 6, k = i & 63;
        int gn = base + n;
        if (gn < NN) g_h[gn * 64 + k] = Ts[n * 68 + k];
    }
    if (tid < 64) {
        float s = 0.f, q = 0.f;
        for (int n = 0; n < 64; n++) {
            float v = Ts[n * 68 + tid];
            s += v;
            q += v * v;
        }
        atomicAdd(&g_sum[tid], (double)s);
        atomicAdd(&g_sq[tid], (double)q);
    }
}

// ---------------- BN stat finalize -> scale/shift ----------------
__global__ void bn_fin_kernel(const float* __restrict__ gamma, const float* __restrict__ beta) {
    int f = threadIdx.x;
    if (f >= DD) return;
    float mu = (float)(g_sum[f] / (double)NN);
    float var = (float)(g_sq[f] / (double)NN) - mu * mu;
    float rstd = rsqrtf(var + 1e-5f);
    float sc = gamma[f] * rstd;
    g_bnp[f] = sc;
    g_bnp[DD + f] = beta[f] - mu * sc;
}

// ---------------- BN apply (+store hbn layer0) + graph pooling ----------------
__global__ void apply_kernel(const int* __restrict__ batch, int layer) {
    int t = blockIdx.x * blockDim.x + threadIdx.x;
    if (t >= NN * 16) return;
    int n = t >> 4, c = t & 15;
    float4 v = reinterpret_cast<const float4*>(g_h)[t];
    float4 s = reinterpret_cast<const float4*>(g_bnp)[c];
    float4 sh = reinterpret_cast<const float4*>(g_bnp)[16 + c];
    float4 hb = make_float4(v.x * s.x + sh.x, v.y * s.y + sh.y,
                            v.z * s.z + sh.z, v.w * s.w + sh.w);
    if (layer == 0) reinterpret_cast<float4*>(g_hbn)[t] = hb;
    int g = batch[n];
    red4(&reinterpret_cast<float4*>(g_pool)[(layer * GG + g) * 16 + c], hb.x, hb.y, hb.z, hb.w);
}

// ---------------- classifier head + log_softmax ----------------
__global__ void head_kernel(const float* __restrict__ wf, const float* __restrict__ bf,
                            const float* __restrict__ wf1, const float* __restrict__ bf1,
                            const float* __restrict__ wf2, const float* __restrict__ bf2,
                            float* __restrict__ out) {
    __shared__ float gs[128];
    __shared__ float as_[64];
    __shared__ float bs[64];
    int g = blockIdx.x;
    int j = threadIdx.x;
    gs[j] = g_pool[g * 64 + j];
    gs[64 + j] = g_pool[(GG + g) * 64 + j];
    __syncthreads();
    float acc = bf[j];
#pragma unroll 8
    for (int k = 0; k < 128; k++) acc += gs[k] * wf[k * 64 + j];
    as_[j] = fmaxf(acc, 0.f);
    __syncthreads();
    acc = bf1[j];
#pragma unroll 8
    for (int k = 0; k < 64; k++) acc += as_[k] * wf1[k * 64 + j];
    bs[j] = fmaxf(acc, 0.f);
    __syncthreads();
    if (j == 0) {
        float l0 = bf2[0], l1 = bf2[1];
        for (int k = 0; k < 64; k++) {
            l0 += bs[k] * wf2[k * 2 + 0];
            l1 += bs[k] * wf2[k * 2 + 1];
        }
        float m = fmaxf(l0, l1);
        float lse = m + logf(expf(l0 - m) + expf(l1 - m));
        out[g * 2 + 0] = l0 - lse;
        out[g * 2 + 1] = l1 - lse;
    }
}

extern "C" void kernel_launch(void* const* d_in, const int* in_sizes, int n_in,
                              void* d_out, int out_size) {
    (void)in_sizes; (void)n_in; (void)out_size;
    const float* x     = (const float*)d_in[0];
    const int*   ei    = (const int*)d_in[1];
    const float* ew    = (const float*)d_in[2];
    const int*   batch = (const int*)d_in[3];
    const float* w1a = (const float*)d_in[4],  *b1a = (const float*)d_in[5];
    const float* w2a = (const float*)d_in[6],  *b2a = (const float*)d_in[7];
    const float* gamma0 = (const float*)d_in[8],  *beta0 = (const float*)d_in[9];
    const float* w1b = (const float*)d_in[10], *b1b = (const float*)d_in[11];
    const float* w2b = (const float*)d_in[12], *b2b = (const float*)d_in[13];
    const float* gamma1 = (const float*)d_in[14], *beta1 = (const float*)d_in[15];
    const float* wf  = (const float*)d_in[16], *bf  = (const float*)d_in[17];
    const float* wf1 = (const float*)d_in[18], *bf1 = (const float*)d_in[19];
    const float* wf2 = (const float*)d_in[20], *bf2 = (const float*)d_in[21];
    float* out = (float*)d_out;

    int zb = (NN * 16 + 255) / 256;
    int nb = (NN + 63) / 64;
    int sb = (EE * 16 + 255) / 256;
    int ab = (NN * 16 + 255) / 256;

    // ---- layer 0 ----
    zero_kernel<<<zb, 256>>>(0);
    gemm_kernel<128><<<nb, 256>>>(x, w1a);          // y = x @ W1a  (project FIRST, then aggregate)
    scatter_kernel<<<sb, 256>>>(ei, ew);            // agg = segsum(ew * y[src])
    mlp2_kernel<<<nb, 256>>>(b1a, w2a, b2a);        // h = relu(relu(y+agg+b1a)@W2a+b2a), stats
    bn_fin_kernel<<<1, 64>>>(gamma0, beta0);
    apply_kernel<<<ab, 256>>>(batch, 0);            // hbn, p0

    // ---- layer 1 ----
    zero_kernel<<<zb, 256>>>(1);
    gemm_kernel<64><<<nb, 256>>>(nullptr, w1b);     // y2 = hbn @ W1b
    scatter_kernel<<<sb, 256>>>(ei, ew);
    mlp2_kernel<<<nb, 256>>>(b1b, w2b, b2b);
    bn_fin_kernel<<<1, 64>>>(gamma1, beta1);
    apply_kernel<<<ab, 256>>>(batch, 1);            // p1

    // ---- head ----
    head_kernel<<<GG, 64>>>(wf, bf, wf1, bf1, wf2, bf2, out);
}

// round 5
// speedup vs baseline: 1.0209x; 1.0209x over previous
#include <cuda_runtime.h>

#define NN 100000
#define EE 1600000
#define FF 128
#define DD 64
#define GG 512

// ---------------- device scratch ----------------
__device__ __align__(16) float g_y[NN * DD];     // projected features
__device__ __align__(16) float g_z[NN * DD];     // relu(y_self + agg + b1)
__device__ __align__(16) float g_h[NN * DD];     // layer-0 pre-BN relu output
__device__ int g_deg[NN];
__device__ int g_cur[NN];
__device__ int g_rowptr[NN + 1];
__device__ int g_cnt[GG];
__device__ __align__(8) int2 g_epack[EE];        // (src, weight bits) CSR-ordered
__device__ double g_sum[DD];
__device__ double g_sq[DD];
__device__ __align__(16) float g_bnp0[2 * DD];   // [scale, shift]
__device__ __align__(16) float g_bnp1[2 * DD];
__device__ __align__(16) float g_pool[2 * GG * DD];  // RAW h pooled sums

__device__ __forceinline__ void red4(float4* p, float x, float y, float z, float w) {
    asm volatile("red.global.add.v4.f32 [%0], {%1,%2,%3,%4};"
                 :: "l"(p), "f"(x), "f"(y), "f"(z), "f"(w) : "memory");
}

// ---------------- zero scratch (once per launch) ----------------
__global__ void zero_kernel() {
    int t = blockIdx.x * blockDim.x + threadIdx.x;
    if (t < NN) g_deg[t] = 0;
    if (t < GG) g_cnt[t] = 0;
    if (t < DD) { g_sum[t] = 0.0; g_sq[t] = 0.0; }
    if (t < 2 * GG * 16)
        reinterpret_cast<float4*>(g_pool)[t] = make_float4(0.f, 0.f, 0.f, 0.f);
}

// ---------------- degree histogram + per-graph node counts ----------------
__global__ void hist_kernel(const int* __restrict__ ei, const int* __restrict__ batch) {
    int t = blockIdx.x * blockDim.x + threadIdx.x;
    if (t < EE) atomicAdd(&g_deg[ei[EE + t]], 1);
    if (t < NN) atomicAdd(&g_cnt[batch[t]], 1);
}

// ---------------- single-block exclusive scan -> rowptr, cursor ----------------
__global__ void scan_kernel() {
    __shared__ int part[512];
    const int CH = (NN + 511) / 512;  // 196
    int tid = threadIdx.x;
    int base = tid * CH;
    int s = 0;
    for (int i = 0; i < CH; i++) {
        int n = base + i;
        if (n < NN) s += g_deg[n];
    }
    part[tid] = s;
    __syncthreads();
    for (int off = 1; off < 512; off <<= 1) {
        int v = (tid >= off) ? part[tid - off] : 0;
        __syncthreads();
        part[tid] += v;
        __syncthreads();
    }
    int run = (tid == 0) ? 0 : part[tid - 1];
    for (int i = 0; i < CH; i++) {
        int n = base + i;
        if (n < NN) {
            g_rowptr[n] = run;
            g_cur[n] = run;
            run += g_deg[n];
        }
    }
    if (tid == 511) g_rowptr[NN] = run;
}

// ---------------- CSR fill: epack[pos] = (src, w) ----------------
__global__ void fill_kernel(const int* __restrict__ ei, const float* __restrict__ ew) {
    int t = blockIdx.x * blockDim.x + threadIdx.x;
    if (t >= EE) return;
    int src = ei[t];
    int dst = ei[EE + t];
    float w = ew[t];
    int pos = atomicAdd(&g_cur[dst], 1);
    g_epack[pos] = make_int2(src, __float_as_int(w));
}

// ---------------- C[N x 64] = A[N x K] @ W[K x 64] -> g_y ----------------
// BN=true: A is g_h, transformed by g_bnp0 (scale/shift) on load (K must be 64).
template <int K, bool BN>
__global__ void gemm_kernel(const float* __restrict__ Ain, const float* __restrict__ W) {
    __shared__ float As[64 * 68];
    __shared__ float Ws[64 * 64];
    const float* A = BN ? g_h : Ain;
    int base = blockIdx.x * 64;
    int tid = threadIdx.x;
    int ty = tid >> 4, tx = tid & 15;
    const int KF4 = K / 4;
    float acc[4][4] = {};
    for (int kc = 0; kc < K; kc += 64) {
        for (int i = tid; i < 1024; i += 256) {
            int n = i >> 4, k4 = i & 15;
            int gn = base + n;
            float4 v = make_float4(0.f, 0.f, 0.f, 0.f);
            if (gn < NN) v = reinterpret_cast<const float4*>(A)[(size_t)gn * KF4 + (kc >> 2) + k4];
            if (BN) {
                float4 sc = reinterpret_cast<const float4*>(g_bnp0)[k4];
                float4 sh = reinterpret_cast<const float4*>(g_bnp0)[16 + k4];
                v.x = v.x * sc.x + sh.x; v.y = v.y * sc.y + sh.y;
                v.z = v.z * sc.z + sh.z; v.w = v.w * sc.w + sh.w;
            }
            *reinterpret_cast<float4*>(&As[n * 68 + k4 * 4]) = v;
        }
        for (int i = tid; i < 1024; i += 256) {
            int k = i >> 4, j4 = i & 15;
            reinterpret_cast<float4*>(Ws)[k * 16 + j4] =
                reinterpret_cast<const float4*>(W)[(size_t)(kc + k) * 16 + j4];
        }
        __syncthreads();
#pragma unroll 8
        for (int k = 0; k < 64; k++) {
            float a[4];
#pragma unroll
            for (int r = 0; r < 4; r++) a[r] = As[(ty * 4 + r) * 68 + k];
            float4 b = *reinterpret_cast<const float4*>(&Ws[k * 64 + tx * 4]);
            float bv[4] = {b.x, b.y, b.z, b.w};
#pragma unroll
            for (int r = 0; r < 4; r++)
#pragma unroll
                for (int c = 0; c < 4; c++) acc[r][c] += a[r] * bv[c];
        }
        __syncthreads();
    }
#pragma unroll
    for (int r = 0; r < 4; r++) {
        int gn = base + ty * 4 + r;
        if (gn < NN)
            reinterpret_cast<float4*>(g_y)[gn * 16 + tx] =
                make_float4(acc[r][0], acc[r][1], acc[r][2], acc[r][3]);
    }
}

// ---------------- CSR aggregation: g_z = relu(y_self + sum w*y[src] + b1) ----------------
__global__ void agg_kernel(const float* __restrict__ b1) {
    int t = blockIdx.x * blockDim.x + threadIdx.x;
    int node = t >> 4, c = t & 15;
    if (node >= NN) return;
    int start = g_rowptr[node];
    int end = g_rowptr[node + 1];
    const float4* Y4 = reinterpret_cast<const float4*>(g_y);
    float4 acc = Y4[node * 16 + c];
    int i = start;
    for (; i + 2 <= end; i += 2) {
        int2 e0 = g_epack[i];
        int2 e1 = g_epack[i + 1];
        float4 v0 = Y4[e0.x * 16 + c];
        float4 v1 = Y4[e1.x * 16 + c];
        float w0 = __int_as_float(e0.y);
        float w1 = __int_as_float(e1.y);
        acc.x += w0 * v0.x + w1 * v1.x;
        acc.y += w0 * v0.y + w1 * v1.y;
        acc.z += w0 * v0.z + w1 * v1.z;
        acc.w += w0 * v0.w + w1 * v1.w;
    }
    if (i < end) {
        int2 e0 = g_epack[i];
        float4 v0 = Y4[e0.x * 16 + c];
        float w0 = __int_as_float(e0.y);
        acc.x += w0 * v0.x; acc.y += w0 * v0.y;
        acc.z += w0 * v0.z; acc.w += w0 * v0.w;
    }
    float4 bb = reinterpret_cast<const float4*>(b1)[c];
    reinterpret_cast<float4*>(g_z)[node * 16 + c] =
        make_float4(fmaxf(acc.x + bb.x, 0.f), fmaxf(acc.y + bb.y, 0.f),
                    fmaxf(acc.z + bb.z, 0.f), fmaxf(acc.w + bb.w, 0.f));
}

// ---------------- h = relu(g_z @ W2 + b2); BN stats; RAW pooling ----------------
template <bool STORE>
__global__ void mlp2_kernel(const float* __restrict__ W2, const float* __restrict__ b2,
                            const int* __restrict__ batch, int layer) {
    __shared__ float Ts[64 * 68];
    __shared__ float Ws[64 * 64];
    __shared__ float s_stat[128];
    int base = blockIdx.x * 64;
    int tid = threadIdx.x;
    if (tid < 128) s_stat[tid] = 0.f;
    for (int i = tid; i < 1024; i += 256) {
        int n = i >> 4, k4 = i & 15;
        int gn = base + n;
        float4 v = make_float4(0.f, 0.f, 0.f, 0.f);
        if (gn < NN) v = reinterpret_cast<const float4*>(g_z)[gn * 16 + k4];
        *reinterpret_cast<float4*>(&Ts[n * 68 + k4 * 4]) = v;
    }
    for (int i = tid; i < 1024; i += 256)
        reinterpret_cast<float4*>(Ws)[i] = reinterpret_cast<const float4*>(W2)[i];
    __syncthreads();
    int ty = tid >> 4, tx = tid & 15;
    float acc[4][4] = {};
#pragma unroll 8
    for (int k = 0; k < 64; k++) {
        float a[4];
#pragma unroll
        for (int r = 0; r < 4; r++) a[r] = Ts[(ty * 4 + r) * 68 + k];
        float4 b = *reinterpret_cast<const float4*>(&Ws[k * 64 + tx * 4]);
        float bv[4] = {b.x, b.y, b.z, b.w};
#pragma unroll
        for (int r = 0; r < 4; r++)
#pragma unroll
            for (int c = 0; c < 4; c++) acc[r][c] += a[r] * bv[c];
    }
    float4 bb = *reinterpret_cast<const float4*>(&b2[tx * 4]);
    float bbv[4] = {bb.x, bb.y, bb.z, bb.w};
    float cs[4] = {0.f, 0.f, 0.f, 0.f};
    float cq[4] = {0.f, 0.f, 0.f, 0.f};
#pragma unroll
    for (int r = 0; r < 4; r++) {
        int gn = base + ty * 4 + r;
        if (gn < NN) {
            float v[4];
#pragma unroll
            for (int c = 0; c < 4; c++) {
                v[c] = fmaxf(acc[r][c] + bbv[c], 0.f);
                cs[c] += v[c];
                cq[c] += v[c] * v[c];
            }
            if (STORE)
                reinterpret_cast<float4*>(g_h)[gn * 16 + tx] =
                    make_float4(v[0], v[1], v[2], v[3]);
            int g = batch[gn];
            red4(&reinterpret_cast<float4*>(g_pool)[(layer * GG + g) * 16 + tx],
                 v[0], v[1], v[2], v[3]);
        }
    }
#pragma unroll
    for (int c = 0; c < 4; c++) {
        atomicAdd(&s_stat[tx * 4 + c], cs[c]);
        atomicAdd(&s_stat[64 + tx * 4 + c], cq[c]);
    }
    __syncthreads();
    if (tid < 64) {
        atomicAdd(&g_sum[tid], (double)s_stat[tid]);
        atomicAdd(&g_sq[tid], (double)s_stat[64 + tid]);
    }
}

// ---------------- BN finalize -> scale/shift; reset stats ----------------
__global__ void bn_fin_kernel(const float* __restrict__ gamma, const float* __restrict__ beta,
                              int layer) {
    int f = threadIdx.x;
    if (f >= DD) return;
    double s = g_sum[f], q = g_sq[f];
    g_sum[f] = 0.0; g_sq[f] = 0.0;
    float mu = (float)(s / (double)NN);
    float var = (float)(q / (double)NN) - mu * mu;
    float rstd = rsqrtf(var + 1e-5f);
    float sc = gamma[f] * rstd;
    float* bp = layer ? g_bnp1 : g_bnp0;
    bp[f] = sc;
    bp[DD + f] = beta[f] - mu * sc;
}

// ---------------- classifier head: BN-corrected pooling + MLP + log_softmax ----------------
__global__ void head_kernel(const float* __restrict__ wf, const float* __restrict__ bf,
                            const float* __restrict__ wf1, const float* __restrict__ bf1,
                            const float* __restrict__ wf2, const float* __restrict__ bf2,
                            float* __restrict__ out) {
    __shared__ float gs[128];
    __shared__ float as_[64];
    __shared__ float bs[64];
    int g = blockIdx.x;
    int j = threadIdx.x;
    float cnt = (float)g_cnt[g];
    gs[j]      = g_pool[g * 64 + j] * g_bnp0[j] + cnt * g_bnp0[64 + j];
    gs[64 + j] = g_pool[(GG + g) * 64 + j] * g_bnp1[j] + cnt * g_bnp1[64 + j];
    __syncthreads();
    float acc = bf[j];
#pragma unroll 8
    for (int k = 0; k < 128; k++) acc += gs[k] * wf[k * 64 + j];
    as_[j] = fmaxf(acc, 0.f);
    __syncthreads();
    acc = bf1[j];
#pragma unroll 8
    for (int k = 0; k < 64; k++) acc += as_[k] * wf1[k * 64 + j];
    bs[j] = fmaxf(acc, 0.f);
    __syncthreads();
    if (j == 0) {
        float l0 = bf2[0], l1 = bf2[1];
        for (int k = 0; k < 64; k++) {
            l0 += bs[k] * wf2[k * 2 + 0];
            l1 += bs[k] * wf2[k * 2 + 1];
        }
        float m = fmaxf(l0, l1);
        float lse = m + logf(expf(l0 - m) + expf(l1 - m));
        out[g * 2 + 0] = l0 - lse;
        out[g * 2 + 1] = l1 - lse;
    }
}

extern "C" void kernel_launch(void* const* d_in, const int* in_sizes, int n_in,
                              void* d_out, int out_size) {
    (void)in_sizes; (void)n_in; (void)out_size;
    const float* x     = (const float*)d_in[0];
    const int*   ei    = (const int*)d_in[1];
    const float* ew    = (const float*)d_in[2];
    const int*   batch = (const int*)d_in[3];
    const float* w1a = (const float*)d_in[4],  *b1a = (const float*)d_in[5];
    const float* w2a = (const float*)d_in[6],  *b2a = (const float*)d_in[7];
    const float* gamma0 = (const float*)d_in[8],  *beta0 = (const float*)d_in[9];
    const float* w1b = (const float*)d_in[10], *b1b = (const float*)d_in[11];
    const float* w2b = (const float*)d_in[12], *b2b = (const float*)d_in[13];
    const float* gamma1 = (const float*)d_in[14], *beta1 = (const float*)d_in[15];
    const float* wf  = (const float*)d_in[16], *bf  = (const float*)d_in[17];
    const float* wf1 = (const float*)d_in[18], *bf1 = (const float*)d_in[19];
    const float* wf2 = (const float*)d_in[20], *bf2 = (const float*)d_in[21];
    float* out = (float*)d_out;

    int nb = (NN + 63) / 64;               // 1563
    int eb = (EE + 255) / 256;             // 6250
    int ab = (NN * 16 + 255) / 256;        // 6250
    int zb = (NN + 255) / 256;

    // ---- CSR build (once, reused by both layers) ----
    zero_kernel<<<zb, 256>>>();
    hist_kernel<<<eb, 256>>>(ei, batch);
    scan_kernel<<<1, 512>>>();
    fill_kernel<<<eb, 256>>>(ei, ew);

    // ---- layer 0 ----
    gemm_kernel<128, false><<<nb, 256>>>(x, w1a);   // y = x @ W1a (project first)
    agg_kernel<<<ab, 256>>>(b1a);                   // z = relu(y + gather + b1a)
    mlp2_kernel<true><<<nb, 256>>>(w2a, b2a, batch, 0);
    bn_fin_kernel<<<1, 64>>>(gamma0, beta0, 0);

    // ---- layer 1 ----
    gemm_kernel<64, true><<<nb, 256>>>(nullptr, w1b);  // y = BN0(h) @ W1b, BN fused in load
    agg_kernel<<<ab, 256>>>(b1b);
    mlp2_kernel<false><<<nb, 256>>>(w2b, b2b, batch, 1);
    bn_fin_kernel<<<1, 64>>>(gamma1, beta1, 1);

    // ---- head ----
    head_kernel<<<GG, 64>>>(wf, bf, wf1, bf1, wf2, bf2, out);
}